// round 16
// baseline (speedup 1.0000x reference)
#include <cuda_runtime.h>
#include <cuda_fp16.h>
#include <mma.h>
#include <math.h>

using namespace nvcuda;

#define NN 100000
#define NH 50000                      // half the nodes (2 nodes per thread in aggs)
#define NN_PAD 100224                 // padded rows for wmma tile stores
#define EE 3200000
#define NBLK ((NN + 255) / 256)
#define SCAN_B 1024
#define NSCAN ((NN + SCAN_B - 1) / SCAN_B)   // 98

// ---------------- device scratch (static; no allocation allowed) -----------
__device__ int    g_is64;
__device__ int    g_srt[EE];           // CSR: src sorted by dst
__device__ int    g_deg[NN];
__device__ int    g_row[NN + 1];
__device__ int    g_cursor[NN];
__device__ int    g_blk[NSCAN];
__device__ int    g_blkoff[NSCAN];
__device__ float  g_dinv[NN];
__device__ float  g_hf[NN_PAD * 16];   // fp32 gemm output (pre-scale, padded)
__device__ __half g_h[NN * 16];        // hs = (x@W1)*dinv, fp16
__device__ __half g_h2[NN * 16];       // zs = relu(agg1+b1)*dinv, fp16
__device__ float  g_agg[NN * 16];      // agg_z, fp32

// ---------------- edge dtype probe (int64 vs int32) ------------------------
__global__ void k_detect(const long long* e) {
    __shared__ int bad;
    if (threadIdx.x == 0) bad = 0;
    __syncthreads();
    long long v = e[threadIdx.x];
    if (v < 0 || v >= (long long)NN) atomicOr(&bad, 1);
    __syncthreads();
    if (threadIdx.x == 0) g_is64 = bad ? 0 : 1;
}

// degree histogram: 4 edges per thread, batched loads before atomics
__global__ void k_deg(const void* eptr) {
    int i = blockIdx.x * 256 + threadIdx.x;
    int d0, d1, d2, d3;
    if (g_is64) {
        const longlong2* p = reinterpret_cast<const longlong2*>(
            (const long long*)eptr + EE);
        longlong2 a = p[i * 2];
        longlong2 b = p[i * 2 + 1];
        d0 = (int)a.x; d1 = (int)a.y; d2 = (int)b.x; d3 = (int)b.y;
    } else {
        const int4* p = reinterpret_cast<const int4*>((const int*)eptr + EE);
        int4 a = p[i];
        d0 = a.x; d1 = a.y; d2 = a.z; d3 = a.w;
    }
    atomicAdd(&g_deg[d0], 1);
    atomicAdd(&g_deg[d1], 1);
    atomicAdd(&g_deg[d2], 1);
    atomicAdd(&g_deg[d3], 1);
}

// ---------------- exclusive scan of g_deg -> g_row --------------------------
__global__ void k_scan1() {
    __shared__ int wsum[32];
    int i = blockIdx.x * SCAN_B + threadIdx.x;
    int v = (i < NN) ? g_deg[i] : 0;
    int lane = threadIdx.x & 31, warp = threadIdx.x >> 5;
    int s = v;
#pragma unroll
    for (int off = 1; off < 32; off <<= 1) {
        int t = __shfl_up_sync(0xffffffffu, s, off);
        if (lane >= off) s += t;
    }
    if (lane == 31) wsum[warp] = s;
    __syncthreads();
    if (warp == 0) {
        int w = wsum[lane];
#pragma unroll
        for (int off = 1; off < 32; off <<= 1) {
            int t = __shfl_up_sync(0xffffffffu, w, off);
            if (lane >= off) w += t;
        }
        wsum[lane] = w;
    }
    __syncthreads();
    int incl = s + (warp ? wsum[warp - 1] : 0);
    if (i < NN) g_row[i] = incl - v;
    if (threadIdx.x == SCAN_B - 1) g_blk[blockIdx.x] = incl;
}

__global__ void k_scan2() {
    __shared__ int sh[128];
    int t = threadIdx.x;
    int v = (t < NSCAN) ? g_blk[t] : 0;
    sh[t] = v;
    __syncthreads();
#pragma unroll
    for (int off = 1; off < 128; off <<= 1) {
        int u = (t >= off) ? sh[t - off] : 0;
        __syncthreads();
        sh[t] += u;
        __syncthreads();
    }
    if (t < NSCAN) g_blkoff[t] = sh[t] - v;
}

__global__ void k_scan3() {
    int i = blockIdx.x * 256 + threadIdx.x;
    if (i < NN) {
        int r = g_row[i] + g_blkoff[i >> 10];
        g_row[i] = r;
        g_cursor[i] = r;
        g_dinv[i] = rsqrtf((float)g_deg[i] + 1.0f);   // +1 self loop
    }
    if (i == 0) g_row[NN] = EE;
}

// counting-sort fill: 4 edges per thread
__global__ void k_sortfill(const void* eptr) {
    int i = blockIdx.x * 256 + threadIdx.x;
    int s0, s1, s2, s3, d0, d1, d2, d3;
    if (g_is64) {
        const longlong2* ps = reinterpret_cast<const longlong2*>((const long long*)eptr);
        const longlong2* pd = reinterpret_cast<const longlong2*>((const long long*)eptr + EE);
        longlong2 a = ps[i * 2], b = ps[i * 2 + 1];
        longlong2 c = pd[i * 2], d = pd[i * 2 + 1];
        s0 = (int)a.x; s1 = (int)a.y; s2 = (int)b.x; s3 = (int)b.y;
        d0 = (int)c.x; d1 = (int)c.y; d2 = (int)d.x; d3 = (int)d.y;
    } else {
        const int4* ps = reinterpret_cast<const int4*>((const int*)eptr);
        const int4* pd = reinterpret_cast<const int4*>((const int*)eptr + EE);
        int4 a = ps[i], c = pd[i];
        s0 = a.x; s1 = a.y; s2 = a.z; s3 = a.w;
        d0 = c.x; d1 = c.y; d2 = c.z; d3 = c.w;
    }
    int p0 = atomicAdd(&g_cursor[d0], 1);
    int p1 = atomicAdd(&g_cursor[d1], 1);
    int p2 = atomicAdd(&g_cursor[d2], 1);
    int p3 = atomicAdd(&g_cursor[d3], 1);
    g_srt[p0] = s0;
    g_srt[p1] = s1;
    g_srt[p2] = s2;
    g_srt[p3] = s3;
}

// ---------------- GEMM1: g_hf = x @ W1 via wmma (HMMA, fp32 accum) ---------
#define A_STRIDE 48   // half elements per staged row (96B: 32B-aligned rows)
__global__ void k_gemm1(const float* __restrict__ x, const float* __restrict__ W1) {
    __shared__ __align__(32) __half Wh[512 * 16];            // 16 KB
    __shared__ __align__(32) __half Ah[128 * A_STRIDE];      // 12 KB

    int tid = threadIdx.x;
    int warp = tid >> 5;
    int rowBase = blockIdx.x * 128;

    for (int i = tid; i < 512 * 16 / 2; i += 128) {
        float2 w = reinterpret_cast<const float2*>(W1)[i];
        reinterpret_cast<__half2*>(Wh)[i] = __floats2half2_rn(w.x, w.y);
    }
    __syncthreads();

    wmma::fragment<wmma::accumulator, 16, 16, 16, float> acc0, acc1;
    wmma::fill_fragment(acc0, 0.0f);
    wmma::fill_fragment(acc1, 0.0f);

    const float4* xg = reinterpret_cast<const float4*>(x);

    for (int ch = 0; ch < 16; ch++) {                 // 16 chunks x 32 k
#pragma unroll
        for (int p = 0; p < 8; p++) {
            int f = tid + 128 * p;                    // 0..1023
            int r = f >> 3, c4 = f & 7;
            int gr = rowBase + r;
            if (gr >= NN) gr = NN - 1;                // clamp (no early return)
            float4 v = xg[(size_t)gr * 128 + ch * 8 + c4];
            __half2* dst = reinterpret_cast<__half2*>(&Ah[r * A_STRIDE + c4 * 4]);
            dst[0] = __floats2half2_rn(v.x, v.y);
            dst[1] = __floats2half2_rn(v.z, v.w);
        }
        __syncthreads();

#pragma unroll
        for (int ks = 0; ks < 2; ks++) {              // 2 k-steps of 16
            wmma::fragment<wmma::matrix_b, 16, 16, 16, __half, wmma::row_major> bf;
            wmma::load_matrix_sync(bf, Wh + (ch * 32 + ks * 16) * 16, 16);

            wmma::fragment<wmma::matrix_a, 16, 16, 16, __half, wmma::row_major> af;
            wmma::load_matrix_sync(af, Ah + (warp * 32) * A_STRIDE + ks * 16, A_STRIDE);
            wmma::mma_sync(acc0, af, bf, acc0);

            wmma::load_matrix_sync(af, Ah + (warp * 32 + 16) * A_STRIDE + ks * 16, A_STRIDE);
            wmma::mma_sync(acc1, af, bf, acc1);
        }
        __syncthreads();
    }

    wmma::store_matrix_sync(g_hf + (size_t)(rowBase + warp * 32) * 16, acc0,
                            16, wmma::mem_row_major);
    wmma::store_matrix_sync(g_hf + (size_t)(rowBase + warp * 32 + 16) * 16, acc1,
                            16, wmma::mem_row_major);
}

// scale by dinv and convert to fp16 (side stream, after gemm + scan3)
__global__ void k_scale() {
    int t = blockIdx.x * 256 + threadIdx.x;   // quad index: node*4 + j
    int node = t >> 2;
    if (node >= NN) return;
    float s = g_dinv[node];
    float4 v = reinterpret_cast<const float4*>(g_hf)[t];
    __half2 a = __floats2half2_rn(v.x * s, v.y * s);
    __half2 b = __floats2half2_rn(v.z * s, v.w * s);
    uint2 u;
    u.x = *reinterpret_cast<unsigned*>(&a);
    u.y = *reinterpret_cast<unsigned*>(&b);
    reinterpret_cast<uint2*>(g_h)[t] = u;
}

// ---------------- CSR aggregation: 2 nodes per thread, fp16 gather ---------
// thread t handles nodes nA = t>>2 and nB = nA + NH, feature quad j = t&3.
// Interleaved gather streams double in-flight loads; 200k threads = 1 wave.
__device__ __forceinline__ void acc_half4(float4& acc, uint2 u) {
    float2 f0 = __half22float2(*reinterpret_cast<__half2*>(&u.x));
    float2 f1 = __half22float2(*reinterpret_cast<__half2*>(&u.y));
    acc.x += f0.x; acc.y += f0.y; acc.z += f1.x; acc.w += f1.y;
}

template <int EPI>
__device__ __forceinline__ void agg2_body(const __half* __restrict__ src,
                                          void* __restrict__ dst,
                                          const float* __restrict__ b1) {
    int t = blockIdx.x * 256 + threadIdx.x;
    int nA = t >> 2;
    int j = t & 3;
    if (nA >= NH) return;
    int nB = nA + NH;

    const uint2* hs = reinterpret_cast<const uint2*>(src);
    int eA = g_row[nA], endA = g_row[nA + 1];
    int eB = g_row[nB], endB = g_row[nB + 1];

    float4 accA = make_float4(0.f, 0.f, 0.f, 0.f);
    float4 accB = make_float4(0.f, 0.f, 0.f, 0.f);
    acc_half4(accA, hs[nA * 4 + j]);               // self-loop terms
    acc_half4(accB, hs[nB * 4 + j]);

    // interleaved main loop: 4 gathers per node per iteration (8 in flight)
    while (eA + 4 <= endA && eB + 4 <= endB) {
        int a0 = g_srt[eA], a1 = g_srt[eA + 1], a2 = g_srt[eA + 2], a3 = g_srt[eA + 3];
        int b0 = g_srt[eB], b1i = g_srt[eB + 1], b2 = g_srt[eB + 2], b3 = g_srt[eB + 3];
        uint2 uA0 = hs[a0 * 4 + j];
        uint2 uB0 = hs[b0 * 4 + j];
        uint2 uA1 = hs[a1 * 4 + j];
        uint2 uB1 = hs[b1i * 4 + j];
        uint2 uA2 = hs[a2 * 4 + j];
        uint2 uB2 = hs[b2 * 4 + j];
        uint2 uA3 = hs[a3 * 4 + j];
        uint2 uB3 = hs[b3 * 4 + j];
        acc_half4(accA, uA0); acc_half4(accA, uA1);
        acc_half4(accA, uA2); acc_half4(accA, uA3);
        acc_half4(accB, uB0); acc_half4(accB, uB1);
        acc_half4(accB, uB2); acc_half4(accB, uB3);
        eA += 4; eB += 4;
    }
    // finish A (unroll-4 then scalar)
    for (; eA + 4 <= endA; eA += 4) {
        int a0 = g_srt[eA], a1 = g_srt[eA + 1], a2 = g_srt[eA + 2], a3 = g_srt[eA + 3];
        uint2 u0 = hs[a0 * 4 + j];
        uint2 u1 = hs[a1 * 4 + j];
        uint2 u2 = hs[a2 * 4 + j];
        uint2 u3 = hs[a3 * 4 + j];
        acc_half4(accA, u0); acc_half4(accA, u1);
        acc_half4(accA, u2); acc_half4(accA, u3);
    }
    for (; eA < endA; ++eA) acc_half4(accA, hs[g_srt[eA] * 4 + j]);
    // finish B
    for (; eB + 4 <= endB; eB += 4) {
        int b0 = g_srt[eB], b1i = g_srt[eB + 1], b2 = g_srt[eB + 2], b3 = g_srt[eB + 3];
        uint2 u0 = hs[b0 * 4 + j];
        uint2 u1 = hs[b1i * 4 + j];
        uint2 u2 = hs[b2 * 4 + j];
        uint2 u3 = hs[b3 * 4 + j];
        acc_half4(accB, u0); acc_half4(accB, u1);
        acc_half4(accB, u2); acc_half4(accB, u3);
    }
    for (; eB < endB; ++eB) acc_half4(accB, hs[g_srt[eB] * 4 + j]);

    float diA = g_dinv[nA];
    float diB = g_dinv[nB];
    if (EPI == 0) {
        float4 bj = __ldg(&reinterpret_cast<const float4*>(b1)[j]);
        uint2* o = reinterpret_cast<uint2*>(dst);
        {
            float zx = fmaxf(accA.x * diA + bj.x, 0.0f) * diA;
            float zy = fmaxf(accA.y * diA + bj.y, 0.0f) * diA;
            float zz = fmaxf(accA.z * diA + bj.z, 0.0f) * diA;
            float zw = fmaxf(accA.w * diA + bj.w, 0.0f) * diA;
            __half2 a = __floats2half2_rn(zx, zy);
            __half2 b = __floats2half2_rn(zz, zw);
            uint2 u;
            u.x = *reinterpret_cast<unsigned*>(&a);
            u.y = *reinterpret_cast<unsigned*>(&b);
            o[nA * 4 + j] = u;
        }
        {
            float zx = fmaxf(accB.x * diB + bj.x, 0.0f) * diB;
            float zy = fmaxf(accB.y * diB + bj.y, 0.0f) * diB;
            float zz = fmaxf(accB.z * diB + bj.z, 0.0f) * diB;
            float zw = fmaxf(accB.w * diB + bj.w, 0.0f) * diB;
            __half2 a = __floats2half2_rn(zx, zy);
            __half2 b = __floats2half2_rn(zz, zw);
            uint2 u;
            u.x = *reinterpret_cast<unsigned*>(&a);
            u.y = *reinterpret_cast<unsigned*>(&b);
            o[nB * 4 + j] = u;
        }
    } else {
        float4* o = reinterpret_cast<float4*>(dst);
        o[nA * 4 + j] = make_float4(accA.x * diA, accA.y * diA, accA.z * diA, accA.w * diA);
        o[nB * 4 + j] = make_float4(accB.x * diB, accB.y * diB, accB.z * diB, accB.w * diB);
    }
}

__global__ void k_agg_l1(const float* __restrict__ b1) { agg2_body<0>(g_h, g_h2, b1); }
__global__ void k_agg_l2()                             { agg2_body<1>(g_h2, g_agg, nullptr); }

// ---------------- final: out = log_softmax(agg_z @ W2 + b2) ----------------
__global__ void k_final(const float* __restrict__ W2, const float* __restrict__ b2,
                        float* __restrict__ out) {
    __shared__ float W2s[16 * 40];
    __shared__ float b2s[40];
    for (int i = threadIdx.x; i < 16 * 40; i += 256) W2s[i] = W2[i];
    if (threadIdx.x < 40) b2s[threadIdx.x] = b2[threadIdx.x];
    __syncthreads();

    int node = blockIdx.x * 256 + threadIdx.x;
    if (node >= NN) return;

    float z[16];
    const float4* ap = reinterpret_cast<const float4*>(g_agg + (size_t)node * 16);
#pragma unroll
    for (int j4 = 0; j4 < 4; j4++) {
        float4 v = ap[j4];
        z[j4 * 4 + 0] = v.x; z[j4 * 4 + 1] = v.y;
        z[j4 * 4 + 2] = v.z; z[j4 * 4 + 3] = v.w;
    }

    float acc[40];
#pragma unroll
    for (int j = 0; j < 40; j++) acc[j] = b2s[j];
#pragma unroll
    for (int k = 0; k < 16; k++) {
        float zk = z[k];
        const float* wr = &W2s[k * 40];
#pragma unroll
        for (int j = 0; j < 40; j++) acc[j] += zk * wr[j];
    }

    float m = acc[0];
#pragma unroll
    for (int j = 1; j < 40; j++) m = fmaxf(m, acc[j]);
    float ssum = 0.0f;
#pragma unroll
    for (int j = 0; j < 40; j++) ssum += expf(acc[j] - m);
    float lse = m + logf(ssum);

    float* op = out + (size_t)node * 40;
    float o[40];
#pragma unroll
    for (int j = 0; j < 40; j++) o[j] = acc[j] - lse;
#pragma unroll
    for (int j4 = 0; j4 < 10; j4++)
        reinterpret_cast<float4*>(op)[j4] =
            make_float4(o[j4 * 4], o[j4 * 4 + 1], o[j4 * 4 + 2], o[j4 * 4 + 3]);
}

// ---------------- launcher with fork/join onto a side stream ---------------
static cudaStream_t g_s2 = 0;
static cudaEvent_t  g_ev_fork = 0, g_ev_join = 0, g_ev_scan3 = 0;
static void* g_deg_addr = 0;

extern "C" void kernel_launch(void* const* d_in, const int* in_sizes, int n_in,
                              void* d_out, int out_size) {
    const float* x  = (const float*)d_in[0];
    const void*  ei = d_in[1];
    const float* W1 = (const float*)d_in[2];
    const float* b1 = (const float*)d_in[3];
    const float* W2 = (const float*)d_in[4];
    const float* b2 = (const float*)d_in[5];
    float* out = (float*)d_out;

    if (!g_s2) {   // one-time infra setup (first call is uncaptured)
        cudaStreamCreateWithFlags(&g_s2, cudaStreamNonBlocking);
        cudaEventCreateWithFlags(&g_ev_fork, cudaEventDisableTiming);
        cudaEventCreateWithFlags(&g_ev_join, cudaEventDisableTiming);
        cudaEventCreateWithFlags(&g_ev_scan3, cudaEventDisableTiming);
        cudaGetSymbolAddress(&g_deg_addr, g_deg);
    }

    // fork: GEMM1 runs concurrently with the CSR build
    cudaEventRecord(g_ev_fork, 0);
    cudaStreamWaitEvent(g_s2, g_ev_fork, 0);
    k_gemm1<<<(NN + 127) / 128, 128, 0, g_s2>>>(x, W1);

    // CSR build chain on the main stream
    k_detect<<<1, 256>>>((const long long*)ei);
    cudaMemsetAsync(g_deg_addr, 0, NN * sizeof(int), 0);
    k_deg<<<EE / 1024, 256>>>(ei);
    k_scan1<<<NSCAN, SCAN_B>>>();
    k_scan2<<<1, 128>>>();
    k_scan3<<<NBLK, 256>>>();
    cudaEventRecord(g_ev_scan3, 0);
    k_sortfill<<<EE / 1024, 256>>>(ei);

    // side stream: scale+convert h once gemm and scan3 are both done
    cudaStreamWaitEvent(g_s2, g_ev_scan3, 0);
    k_scale<<<(NN * 4 + 255) / 256, 256, 0, g_s2>>>();
    cudaEventRecord(g_ev_join, g_s2);

    // join, then the dependent chain (2-node-per-thread aggs, single wave)
    cudaStreamWaitEvent(0, g_ev_join, 0);
    int agg_blk = (NH * 4 + 255) / 256;
    k_agg_l1<<<agg_blk, 256>>>(b1);
    k_agg_l2<<<agg_blk, 256>>>();
    k_final<<<NBLK, 256>>>(W2, b2, out);
}

// round 17
// speedup vs baseline: 1.1015x; 1.1015x over previous
#include <cuda_runtime.h>
#include <cuda_fp16.h>
#include <mma.h>
#include <math.h>

using namespace nvcuda;

#define NN 100000
#define NN_PAD 100224                 // padded rows for wmma tile stores
#define EE 3200000
#define NBLK ((NN + 255) / 256)
#define SCAN_B 1024
#define NSCAN ((NN + SCAN_B - 1) / SCAN_B)   // 98
#define EGRP (EE / 4)                 // edge-groups of 4 edges: 800000
#define QGRP (EGRP / 4)               // groups per quarter: 200000

// ---------------- device scratch (static; no allocation allowed) -----------
__device__ int    g_is64;
__device__ int    g_srt[EE];           // CSR: src sorted by dst
__device__ int    g_deg4[4 * NN];      // 4-way privatized degree histogram
__device__ int    g_cur4[4 * NN];      // 4 cursor arrays (disjoint sub-ranges)
__device__ int    g_row[NN + 1];
__device__ int    g_blk[NSCAN];
__device__ int    g_blkoff[NSCAN];
__device__ float  g_dinv[NN];
__device__ float  g_hf[NN_PAD * 16];   // fp32 gemm output (pre-scale, padded)
__device__ __half g_h[NN * 16];        // hs = (x@W1)*dinv, fp16
__device__ __half g_h2[NN * 16];       // zs = relu(agg1+b1)*dinv, fp16
__device__ float  g_agg[NN * 16];      // agg_z, fp32

// ---------------- edge dtype probe (int64 vs int32) ------------------------
__global__ void k_detect(const long long* e) {
    __shared__ int bad;
    if (threadIdx.x == 0) bad = 0;
    __syncthreads();
    long long v = e[threadIdx.x];
    if (v < 0 || v >= (long long)NN) atomicOr(&bad, 1);
    __syncthreads();
    if (threadIdx.x == 0) g_is64 = bad ? 0 : 1;
}

// degree histogram: 4 edges per thread into quarter-private copy
__global__ void k_deg(const void* eptr) {
    int i = blockIdx.x * 256 + threadIdx.x;       // edge-group index
    int q = i / QGRP;                             // quarter 0..3
    int* deg = g_deg4 + q * NN;
    int d0, d1, d2, d3;
    if (g_is64) {
        const longlong2* p = reinterpret_cast<const longlong2*>(
            (const long long*)eptr + EE);
        longlong2 a = p[i * 2];
        longlong2 b = p[i * 2 + 1];
        d0 = (int)a.x; d1 = (int)a.y; d2 = (int)b.x; d3 = (int)b.y;
    } else {
        const int4* p = reinterpret_cast<const int4*>((const int*)eptr + EE);
        int4 a = p[i];
        d0 = a.x; d1 = a.y; d2 = a.z; d3 = a.w;
    }
    atomicAdd(&deg[d0], 1);
    atomicAdd(&deg[d1], 1);
    atomicAdd(&deg[d2], 1);
    atomicAdd(&deg[d3], 1);
}

// ---------------- exclusive scan of summed deg -> g_row ---------------------
__global__ void k_scan1() {
    __shared__ int wsum[32];
    int i = blockIdx.x * SCAN_B + threadIdx.x;
    int v = 0;
    if (i < NN)
        v = g_deg4[i] + g_deg4[NN + i] + g_deg4[2 * NN + i] + g_deg4[3 * NN + i];
    int lane = threadIdx.x & 31, warp = threadIdx.x >> 5;
    int s = v;
#pragma unroll
    for (int off = 1; off < 32; off <<= 1) {
        int t = __shfl_up_sync(0xffffffffu, s, off);
        if (lane >= off) s += t;
    }
    if (lane == 31) wsum[warp] = s;
    __syncthreads();
    if (warp == 0) {
        int w = wsum[lane];
#pragma unroll
        for (int off = 1; off < 32; off <<= 1) {
            int t = __shfl_up_sync(0xffffffffu, w, off);
            if (lane >= off) w += t;
        }
        wsum[lane] = w;
    }
    __syncthreads();
    int incl = s + (warp ? wsum[warp - 1] : 0);
    if (i < NN) g_row[i] = incl - v;
    if (threadIdx.x == SCAN_B - 1) g_blk[blockIdx.x] = incl;
}

__global__ void k_scan2() {
    __shared__ int sh[128];
    int t = threadIdx.x;
    int v = (t < NSCAN) ? g_blk[t] : 0;
    sh[t] = v;
    __syncthreads();
#pragma unroll
    for (int off = 1; off < 128; off <<= 1) {
        int u = (t >= off) ? sh[t - off] : 0;
        __syncthreads();
        sh[t] += u;
        __syncthreads();
    }
    if (t < NSCAN) g_blkoff[t] = sh[t] - v;
}

// apply block offsets; emit 4 pre-partitioned cursors + dinv
__global__ void k_scan3() {
    int i = blockIdx.x * 256 + threadIdx.x;
    if (i < NN) {
        int r = g_row[i] + g_blkoff[i >> 10];
        g_row[i] = r;
        int d0 = g_deg4[i];
        int d1 = g_deg4[NN + i];
        int d2 = g_deg4[2 * NN + i];
        int d3 = g_deg4[3 * NN + i];
        g_cur4[i]          = r;
        g_cur4[NN + i]     = r + d0;
        g_cur4[2 * NN + i] = r + d0 + d1;
        g_cur4[3 * NN + i] = r + d0 + d1 + d2;
        g_dinv[i] = rsqrtf((float)(d0 + d1 + d2 + d3) + 1.0f);   // +1 self loop
    }
    if (i == 0) g_row[NN] = EE;
}

// counting-sort fill: 4 edges per thread, quarter-private cursor
__global__ void k_sortfill(const void* eptr) {
    int i = blockIdx.x * 256 + threadIdx.x;
    int q = i / QGRP;
    int* cur = g_cur4 + q * NN;
    int s0, s1, s2, s3, d0, d1, d2, d3;
    if (g_is64) {
        const longlong2* ps = reinterpret_cast<const longlong2*>((const long long*)eptr);
        const longlong2* pd = reinterpret_cast<const longlong2*>((const long long*)eptr + EE);
        longlong2 a = ps[i * 2], b = ps[i * 2 + 1];
        longlong2 c = pd[i * 2], d = pd[i * 2 + 1];
        s0 = (int)a.x; s1 = (int)a.y; s2 = (int)b.x; s3 = (int)b.y;
        d0 = (int)c.x; d1 = (int)c.y; d2 = (int)d.x; d3 = (int)d.y;
    } else {
        const int4* ps = reinterpret_cast<const int4*>((const int*)eptr);
        const int4* pd = reinterpret_cast<const int4*>((const int*)eptr + EE);
        int4 a = ps[i], c = pd[i];
        s0 = a.x; s1 = a.y; s2 = a.z; s3 = a.w;
        d0 = c.x; d1 = c.y; d2 = c.z; d3 = c.w;
    }
    int p0 = atomicAdd(&cur[d0], 1);
    int p1 = atomicAdd(&cur[d1], 1);
    int p2 = atomicAdd(&cur[d2], 1);
    int p3 = atomicAdd(&cur[d3], 1);
    g_srt[p0] = s0;
    g_srt[p1] = s1;
    g_srt[p2] = s2;
    g_srt[p3] = s3;
}

// ---------------- GEMM1: g_hf = x @ W1 via wmma (HMMA, fp32 accum) ---------
#define A_STRIDE 48   // half elements per staged row (96B: 32B-aligned rows)
__global__ void k_gemm1(const float* __restrict__ x, const float* __restrict__ W1) {
    __shared__ __align__(32) __half Wh[512 * 16];            // 16 KB
    __shared__ __align__(32) __half Ah[128 * A_STRIDE];      // 12 KB

    int tid = threadIdx.x;
    int warp = tid >> 5;
    int rowBase = blockIdx.x * 128;

    for (int i = tid; i < 512 * 16 / 2; i += 128) {
        float2 w = reinterpret_cast<const float2*>(W1)[i];
        reinterpret_cast<__half2*>(Wh)[i] = __floats2half2_rn(w.x, w.y);
    }
    __syncthreads();

    wmma::fragment<wmma::accumulator, 16, 16, 16, float> acc0, acc1;
    wmma::fill_fragment(acc0, 0.0f);
    wmma::fill_fragment(acc1, 0.0f);

    const float4* xg = reinterpret_cast<const float4*>(x);

    for (int ch = 0; ch < 16; ch++) {                 // 16 chunks x 32 k
#pragma unroll
        for (int p = 0; p < 8; p++) {
            int f = tid + 128 * p;                    // 0..1023
            int r = f >> 3, c4 = f & 7;
            int gr = rowBase + r;
            if (gr >= NN) gr = NN - 1;                // clamp (no early return)
            float4 v = xg[(size_t)gr * 128 + ch * 8 + c4];
            __half2* dst = reinterpret_cast<__half2*>(&Ah[r * A_STRIDE + c4 * 4]);
            dst[0] = __floats2half2_rn(v.x, v.y);
            dst[1] = __floats2half2_rn(v.z, v.w);
        }
        __syncthreads();

#pragma unroll
        for (int ks = 0; ks < 2; ks++) {              // 2 k-steps of 16
            wmma::fragment<wmma::matrix_b, 16, 16, 16, __half, wmma::row_major> bf;
            wmma::load_matrix_sync(bf, Wh + (ch * 32 + ks * 16) * 16, 16);

            wmma::fragment<wmma::matrix_a, 16, 16, 16, __half, wmma::row_major> af;
            wmma::load_matrix_sync(af, Ah + (warp * 32) * A_STRIDE + ks * 16, A_STRIDE);
            wmma::mma_sync(acc0, af, bf, acc0);

            wmma::load_matrix_sync(af, Ah + (warp * 32 + 16) * A_STRIDE + ks * 16, A_STRIDE);
            wmma::mma_sync(acc1, af, bf, acc1);
        }
        __syncthreads();
    }

    wmma::store_matrix_sync(g_hf + (size_t)(rowBase + warp * 32) * 16, acc0,
                            16, wmma::mem_row_major);
    wmma::store_matrix_sync(g_hf + (size_t)(rowBase + warp * 32 + 16) * 16, acc1,
                            16, wmma::mem_row_major);
}

// scale by dinv and convert to fp16 (side stream, after gemm + scan3)
__global__ void k_scale() {
    int t = blockIdx.x * 256 + threadIdx.x;   // quad index: node*4 + j
    int node = t >> 2;
    if (node >= NN) return;
    float s = g_dinv[node];
    float4 v = reinterpret_cast<const float4*>(g_hf)[t];
    __half2 a = __floats2half2_rn(v.x * s, v.y * s);
    __half2 b = __floats2half2_rn(v.z * s, v.w * s);
    uint2 u;
    u.x = *reinterpret_cast<unsigned*>(&a);
    u.y = *reinterpret_cast<unsigned*>(&b);
    reinterpret_cast<uint2*>(g_h)[t] = u;
}

// ---------------- CSR aggregation: 4 lanes per node, fp16 gather -----------
__device__ __forceinline__ void acc_half4(float4& acc, uint2 u) {
    float2 f0 = __half22float2(*reinterpret_cast<__half2*>(&u.x));
    float2 f1 = __half22float2(*reinterpret_cast<__half2*>(&u.y));
    acc.x += f0.x; acc.y += f0.y; acc.z += f1.x; acc.w += f1.y;
}

// layer 1: zs = relu(acc*di + b1)*di  (g_h -> g_h2, both fp16)
__global__ void k_agg_l1(const float* __restrict__ b1) {
    int t = blockIdx.x * 256 + threadIdx.x;
    int node = t >> 2;
    int j = t & 3;
    if (node >= NN) return;
    int e = g_row[node];
    int end = g_row[node + 1];
    const uint2* hs = reinterpret_cast<const uint2*>(g_h);

    float4 acc = make_float4(0.f, 0.f, 0.f, 0.f);
    acc_half4(acc, hs[node * 4 + j]);              // self-loop term
    for (; e + 8 <= end; e += 8) {
        int s0 = g_srt[e],     s1 = g_srt[e + 1], s2 = g_srt[e + 2], s3 = g_srt[e + 3];
        int s4 = g_srt[e + 4], s5 = g_srt[e + 5], s6 = g_srt[e + 6], s7 = g_srt[e + 7];
        uint2 u0 = hs[s0 * 4 + j];
        uint2 u1 = hs[s1 * 4 + j];
        uint2 u2 = hs[s2 * 4 + j];
        uint2 u3 = hs[s3 * 4 + j];
        uint2 u4 = hs[s4 * 4 + j];
        uint2 u5 = hs[s5 * 4 + j];
        uint2 u6 = hs[s6 * 4 + j];
        uint2 u7 = hs[s7 * 4 + j];
        acc_half4(acc, u0); acc_half4(acc, u1); acc_half4(acc, u2); acc_half4(acc, u3);
        acc_half4(acc, u4); acc_half4(acc, u5); acc_half4(acc, u6); acc_half4(acc, u7);
    }
    for (; e < end; ++e) acc_half4(acc, hs[g_srt[e] * 4 + j]);

    float di = g_dinv[node];
    float4 bj = __ldg(&reinterpret_cast<const float4*>(b1)[j]);
    float zx = fmaxf(acc.x * di + bj.x, 0.0f) * di;
    float zy = fmaxf(acc.y * di + bj.y, 0.0f) * di;
    float zz = fmaxf(acc.z * di + bj.z, 0.0f) * di;
    float zw = fmaxf(acc.w * di + bj.w, 0.0f) * di;
    __half2 a = __floats2half2_rn(zx, zy);
    __half2 b = __floats2half2_rn(zz, zw);
    uint2 u;
    u.x = *reinterpret_cast<unsigned*>(&a);
    u.y = *reinterpret_cast<unsigned*>(&b);
    reinterpret_cast<uint2*>(g_h2)[node * 4 + j] = u;
}

// layer 2: agg_z = acc*di  (g_h2 fp16 -> g_agg fp32)
__global__ void k_agg_l2() {
    int t = blockIdx.x * 256 + threadIdx.x;
    int node = t >> 2;
    int j = t & 3;
    if (node >= NN) return;
    int e = g_row[node];
    int end = g_row[node + 1];
    const uint2* hs = reinterpret_cast<const uint2*>(g_h2);

    float4 acc = make_float4(0.f, 0.f, 0.f, 0.f);
    acc_half4(acc, hs[node * 4 + j]);
    for (; e + 8 <= end; e += 8) {
        int s0 = g_srt[e],     s1 = g_srt[e + 1], s2 = g_srt[e + 2], s3 = g_srt[e + 3];
        int s4 = g_srt[e + 4], s5 = g_srt[e + 5], s6 = g_srt[e + 6], s7 = g_srt[e + 7];
        uint2 u0 = hs[s0 * 4 + j];
        uint2 u1 = hs[s1 * 4 + j];
        uint2 u2 = hs[s2 * 4 + j];
        uint2 u3 = hs[s3 * 4 + j];
        uint2 u4 = hs[s4 * 4 + j];
        uint2 u5 = hs[s5 * 4 + j];
        uint2 u6 = hs[s6 * 4 + j];
        uint2 u7 = hs[s7 * 4 + j];
        acc_half4(acc, u0); acc_half4(acc, u1); acc_half4(acc, u2); acc_half4(acc, u3);
        acc_half4(acc, u4); acc_half4(acc, u5); acc_half4(acc, u6); acc_half4(acc, u7);
    }
    for (; e < end; ++e) acc_half4(acc, hs[g_srt[e] * 4 + j]);

    float di = g_dinv[node];
    reinterpret_cast<float4*>(g_agg)[node * 4 + j] =
        make_float4(acc.x * di, acc.y * di, acc.z * di, acc.w * di);
}

// ---------------- final: out = log_softmax(agg_z @ W2 + b2) ----------------
__global__ void k_final(const float* __restrict__ W2, const float* __restrict__ b2,
                        float* __restrict__ out) {
    __shared__ float W2s[16 * 40];
    __shared__ float b2s[40];
    for (int i = threadIdx.x; i < 16 * 40; i += 256) W2s[i] = W2[i];
    if (threadIdx.x < 40) b2s[threadIdx.x] = b2[threadIdx.x];
    __syncthreads();

    int node = blockIdx.x * 256 + threadIdx.x;
    if (node >= NN) return;

    float z[16];
    const float4* ap = reinterpret_cast<const float4*>(g_agg + (size_t)node * 16);
#pragma unroll
    for (int j4 = 0; j4 < 4; j4++) {
        float4 v = ap[j4];
        z[j4 * 4 + 0] = v.x; z[j4 * 4 + 1] = v.y;
        z[j4 * 4 + 2] = v.z; z[j4 * 4 + 3] = v.w;
    }

    float acc[40];
#pragma unroll
    for (int j = 0; j < 40; j++) acc[j] = b2s[j];
#pragma unroll
    for (int k = 0; k < 16; k++) {
        float zk = z[k];
        const float* wr = &W2s[k * 40];
#pragma unroll
        for (int j = 0; j < 40; j++) acc[j] += zk * wr[j];
    }

    float m = acc[0];
#pragma unroll
    for (int j = 1; j < 40; j++) m = fmaxf(m, acc[j]);
    float ssum = 0.0f;
#pragma unroll
    for (int j = 0; j < 40; j++) ssum += expf(acc[j] - m);
    float lse = m + logf(ssum);

    float* op = out + (size_t)node * 40;
    float o[40];
#pragma unroll
    for (int j = 0; j < 40; j++) o[j] = acc[j] - lse;
#pragma unroll
    for (int j4 = 0; j4 < 10; j4++)
        reinterpret_cast<float4*>(op)[j4] =
            make_float4(o[j4 * 4], o[j4 * 4 + 1], o[j4 * 4 + 2], o[j4 * 4 + 3]);
}

// ---------------- launcher with fork/join onto a side stream ---------------
static cudaStream_t g_s2 = 0;
static cudaEvent_t  g_ev_fork = 0, g_ev_join = 0, g_ev_scan3 = 0;
static void* g_deg4_addr = 0;

extern "C" void kernel_launch(void* const* d_in, const int* in_sizes, int n_in,
                              void* d_out, int out_size) {
    const float* x  = (const float*)d_in[0];
    const void*  ei = d_in[1];
    const float* W1 = (const float*)d_in[2];
    const float* b1 = (const float*)d_in[3];
    const float* W2 = (const float*)d_in[4];
    const float* b2 = (const float*)d_in[5];
    float* out = (float*)d_out;

    if (!g_s2) {   // one-time infra setup (first call is uncaptured)
        cudaStreamCreateWithFlags(&g_s2, cudaStreamNonBlocking);
        cudaEventCreateWithFlags(&g_ev_fork, cudaEventDisableTiming);
        cudaEventCreateWithFlags(&g_ev_join, cudaEventDisableTiming);
        cudaEventCreateWithFlags(&g_ev_scan3, cudaEventDisableTiming);
        cudaGetSymbolAddress(&g_deg4_addr, g_deg4);
    }

    // fork: GEMM1 runs concurrently with the CSR build
    cudaEventRecord(g_ev_fork, 0);
    cudaStreamWaitEvent(g_s2, g_ev_fork, 0);
    k_gemm1<<<(NN + 127) / 128, 128, 0, g_s2>>>(x, W1);

    // CSR build chain on the main stream (4-way privatized atomics)
    k_detect<<<1, 256>>>((const long long*)ei);
    cudaMemsetAsync(g_deg4_addr, 0, 4 * NN * sizeof(int), 0);
    k_deg<<<EE / 1024, 256>>>(ei);
    k_scan1<<<NSCAN, SCAN_B>>>();
    k_scan2<<<1, 128>>>();
    k_scan3<<<NBLK, 256>>>();
    cudaEventRecord(g_ev_scan3, 0);
    k_sortfill<<<EE / 1024, 256>>>(ei);

    // side stream: scale+convert h once gemm and scan3 are both done
    cudaStreamWaitEvent(g_s2, g_ev_scan3, 0);
    k_scale<<<(NN * 4 + 255) / 256, 256, 0, g_s2>>>();
    cudaEventRecord(g_ev_join, g_s2);

    // join, then the dependent chain
    cudaStreamWaitEvent(0, g_ev_join, 0);
    int blk4 = (NN * 4 + 255) / 256;
    k_agg_l1<<<blk4, 256>>>(b1);
    k_agg_l2<<<blk4, 256>>>();
    k_final<<<NBLK, 256>>>(W2, b2, out);
}